// round 17
// baseline (speedup 1.0000x reference)
#include <cuda_runtime.h>
#include <math.h>

// ---------------- problem constants ----------------
#define BB    4
#define TT    200
#define HOP   120
#define NN    24000          // T*HOP
#define M1    40
#define A1    5
#define HID   256
#define COND  192
#define NCH   8              // 2B channels (0..3 periodic, 4..7 aperiodic)

#define ALPHA 0.466f
#define AAC   0.782844f      // 1 - ALPHA^2
#define P1C   0.4999273f
#define P2C   0.1067005f
#define P3C   0.00956526f
#define P4C   0.0003041358f
#define SRF   24000.0f

// time-segmentation: 1 write frame per group, 3 zero-state warm frames.
// Measured transients: 1.88e-7 @480 warm, 8.6e-6 @360 => rate ~0.032/sample.
// WARMF=2 would be ~4e-4 (too close to 1e-3) => WARMF stays 3.
#define SEG    200           // segments per channel = frames
#define WARMF  3             // warm-up frames
#define TB 8                 // frames per frontend block

// ---------------- scratch (no allocations allowed) ----------------
__device__ float g_bcoef[NCH * TT * M1];   // MLSA coefficients per channel/frame
__device__ float g_eb0[NCH * TT];          // exp(b[0]) per channel/frame
__device__ float g_b1[NCH * TT];           // b[1] per channel/frame
__device__ float g_exc[BB * NN];           // periodic excitation (0.5 * pulse)
// tree-scan levels: 24000,12000,6000,3000,1500,750,375,187,93,46,23,11,5,2,1
#define SCAN_TOTAL 47993
__device__ float g_scanbuf[BB * SCAN_TOTAL];

// ==================================================================
// K1: FUSED frontend + pulse.
//   blocks 0..99   : dense frontend, TB=8 frames per block (weights
//                    reused across 8 frames; accumulation order per
//                    output unchanged; K-loops unrolled x4 for MLP).
//   blocks 100..103: pulse excitation for batch blk-100 — bit-exact
//                    JAX associative_scan tree. Computes f0 itself from
//                    the raw f0s input (same expf expression => bit-
//                    identical), so it has NO dependency on the
//                    frontend blocks. Also zeroes d_out.
// ==================================================================
__global__ __launch_bounds__(256) void k_front_pulse(
    const float* __restrict__ mceps, const float* __restrict__ apdcs,
    const float* __restrict__ f0s,
    const float* __restrict__ Wm,  const float* __restrict__ bm,
    const float* __restrict__ Wa,  const float* __restrict__ ba,
    const float* __restrict__ Wf,  const float* __restrict__ bf,
    const float* __restrict__ Wpa, const float* __restrict__ bpa,
    const float* __restrict__ Wpp, const float* __restrict__ bpp,
    const float* __restrict__ Wrp, const float* __restrict__ brp,
    const float* __restrict__ Wra, const float* __restrict__ bra,
    const float* __restrict__ Wap,
    float* __restrict__ out)
{
    const int blk = blockIdx.x;
    const int tid = threadIdx.x;

    __shared__ float feat[TB][48];          // mcep[40] | apdc[5] | f0
    __shared__ float hsm [TB][HID + 1];
    __shared__ float caa [TB][COND + 1];
    __shared__ float cpp [TB][COND + 1];
    __shared__ float mcp [TB][M1 + 1];
    __shared__ float mca [TB][M1 + 1];
    __shared__ float sf0 [TT];              // pulse blocks: denormed f0

    if (blk >= 100) {
        // ================= PULSE PATH (4 blocks) =================
        const int b   = blk - 100;
        const int NTH = 256;

        // zero this batch's output span (poisoned by harness)
        for (int i = tid; i < NN; i += NTH)
            out[b * NN + i] = 0.f;

        // f0 from raw input (bit-identical to frontend's expression)
        for (int t = tid; t < TT; t += NTH)
            sf0[t] = expf(fmaf(f0s[b * TT + t], 0.25f, 5.0f));
        __syncthreads();

        const int ln[15] = {24000,12000,6000,3000,1500,750,375,187,93,46,23,11,5,2,1};
        int off[15];
        off[0] = 0;
        #pragma unroll
        for (int k = 1; k < 15; k++) off[k] = off[k-1] + ln[k-1];

        float* buf = g_scanbuf + b * SCAN_TOTAL;

        for (int i = tid; i < NN; i += NTH)
            buf[i] = sf0[i / HOP] / SRF;
        __syncthreads();

        for (int k = 0; k < 14; k++) {
            const float* src = buf + off[k];
            float*       dst = buf + off[k+1];
            const int nn1 = ln[k+1];
            for (int i = tid; i < nn1; i += NTH)
                dst[i] = src[2*i] + src[2*i+1];
            __syncthreads();
        }

        for (int k = 13; k >= 0; k--) {
            float*       a = buf + off[k];
            const float* s = buf + off[k+1];
            const int n = ln[k];
            for (int i = tid; i < n; i += NTH) {
                float v;
                if (i & 1)            v = s[i >> 1];
                else if (i == 0)      v = a[0];
                else                  v = s[(i >> 1) - 1] + a[i];
                a[i] = v;
            }
            __syncthreads();
        }

        for (int i = tid; i < NN; i += NTH) {
            float w  = floorf(buf[i]);
            float wp = (i == 0) ? 0.f : floorf(buf[i-1]);
            float f  = sf0[i / HOP];
            float amp = 0.5f * sqrtf(SRF / fmaxf(f, 1.0f));
            g_exc[b * NN + i] = (w > wp) ? amp : 0.f;
        }
        return;
    }

    // ================= FRONTEND PATH (100 blocks) =================
    const int b   = blk / (TT / TB);        // batch
    const int t0  = (blk % (TT / TB)) * TB; // first frame of tile

    for (int idx = tid; idx < TB * 46; idx += 256) {
        int f = idx / 46, j = idx % 46;
        int bt = b * TT + t0 + f;
        float v;
        if (j < M1)       v = mceps[bt * M1 + j];
        else if (j < 45)  v = apdcs[bt * A1 + (j - M1)];
        else              v = f0s[bt];
        feat[f][j] = v;
    }
    __syncthreads();

    {
        float base = bm[tid] + ba[tid] + bf[tid];
        float acc[TB];
        #pragma unroll
        for (int f = 0; f < TB; f++) acc[f] = base;
        #pragma unroll 4
        for (int i = 0; i < M1; i++) {
            float w = Wm[i * HID + tid];
            #pragma unroll
            for (int f = 0; f < TB; f++) acc[f] = fmaf(feat[f][i], w, acc[f]);
        }
        #pragma unroll
        for (int i = 0; i < A1; i++) {
            float w = Wa[i * HID + tid];
            #pragma unroll
            for (int f = 0; f < TB; f++) acc[f] = fmaf(feat[f][M1 + i], w, acc[f]);
        }
        float wf = Wf[tid];
        #pragma unroll
        for (int f = 0; f < TB; f++) {
            acc[f] = fmaf(feat[f][45], wf, acc[f]);
            hsm[f][tid] = acc[f];
        }
    }
    __syncthreads();

    if (tid < COND) {
        float sa[TB], sp[TB];
        float b_a = bpa[tid], b_p = bpp[tid];
        #pragma unroll
        for (int f = 0; f < TB; f++) { sa[f] = b_a; sp[f] = b_p; }
        #pragma unroll 4
        for (int i = 0; i < HID; i++) {
            float wa = Wpa[i * COND + tid];
            float wp = Wpp[i * COND + tid];
            #pragma unroll
            for (int f = 0; f < TB; f++) {
                float h = hsm[f][i];
                sa[f] = fmaf(h, wa, sa[f]);
                sp[f] = fmaf(h, wp, sp[f]);
            }
        }
        #pragma unroll
        for (int f = 0; f < TB; f++) { caa[f][tid] = sa[f]; cpp[f][tid] = sp[f]; }
    }
    __syncthreads();

    if (tid < M1) {
        float rp[TB], ra[TB];
        float b_rp = brp[tid], b_ra = bra[tid];
        #pragma unroll
        for (int f = 0; f < TB; f++) { rp[f] = b_rp; ra[f] = b_ra; }
        #pragma unroll 4
        for (int i = 0; i < COND; i++) {
            float wrp = Wrp[i * M1 + tid];
            float wra = Wra[i * M1 + tid];
            #pragma unroll
            for (int f = 0; f < TB; f++) {
                rp[f] = fmaf(cpp[f][i], wrp, rp[f]);
                ra[f] = fmaf(caa[f][i], wra, ra[f]);
            }
        }
        float apm[TB];
        #pragma unroll
        for (int f = 0; f < TB; f++) apm[f] = 0.f;
        #pragma unroll
        for (int i = 0; i < A1; i++) {
            float w = Wap[i * M1 + tid];
            #pragma unroll
            for (int f = 0; f < TB; f++) apm[f] = fmaf(feat[f][M1 + i], w, apm[f]);
        }
        #pragma unroll
        for (int f = 0; f < TB; f++) {
            float sp_ = feat[f][tid];
            mcp[f][tid] = sp_ + 0.1f * tanhf(rp[f]);
            mca[f][tid] = sp_ + 0.1f * tanhf(ra[f]) + apm[f];
        }
    }
    __syncthreads();

    if (tid < 2 * TB) {
        int f    = tid >> 1;
        int path = tid & 1;
        const float* mc = (path == 0) ? mcp[f] : mca[f];
        int ch = (path == 0) ? b : (4 + b);
        int t  = t0 + f;
        float* dst = g_bcoef + (ch * TT + t) * M1;
        float bbv = 0.f, b1v = 0.f;
        #pragma unroll
        for (int m = M1 - 1; m >= 0; m--) {
            bbv = fmaf(-ALPHA, bbv, mc[m]);
            dst[m] = bbv;
            if (m == 1) b1v = bbv;
        }
        g_eb0[ch * TT + t] = expf(bbv);
        g_b1[ch * TT + t]  = b1v;
    }
}

// ==================================================================
// K3: MLSA synthesis — EIGHT (channel,frame) groups PER WARP
// (byte-identical to the 199.7us-passing kernel).
// ==================================================================
__global__ __launch_bounds__(32, 1) void k_mlsa(const float* __restrict__ noise,
                                                float* __restrict__ out)
{
    const int lane = threadIdx.x;
    const int gid  = blockIdx.x * 8 + (lane >> 2);  // group 0..1599
    const int sub  = lane & 3;                      // tap within group
    const int gb   = lane & 28;                     // group base lane
    const int c    = gid / SEG;                     // channel
    const int s    = gid % SEG;                     // write frame

    // ---- stage-2 tap state ----
    float n[38];
    #pragma unroll
    for (int j = 0; j < 38; j++) n[j] = 0.f;
    float breg[38];
    float d1o = 0.f, xin = 0.f;

    // ---- stage-1 state (replicated within each group) ----
    float x1p = 0.f, npt0 = 0.f, npt1 = 0.f, npt2 = 0.f;
    float na0 = 0.f, na1 = 0.f, na2 = 0.f, na3 = 0.f;

    const float* bc  = g_bcoef + c * TT * M1;
    const bool periodic = (c < 4);
    const float* src = periodic ? (g_exc + c * NN) : (noise + (c - 4) * NN);
    const float sclc = periodic ? 1.0f : 0.5f;
    float* oout = out + (c & 3) * NN;               // batch = c mod 4

    #pragma unroll 1
    for (int k = 0; k <= WARMF; k++) {
        const int fr  = s - WARMF + k;              // may be negative
        const int frc = (fr < 0) ? 0 : fr;          // clamped frame
        const float esc = (fr < 0) ? 0.f : sclc;    // zero-feed pre-history
        const float* bf_ = bc + frc * M1;
        const float eb0 = g_eb0[c * TT + frc];
        const float b1  = g_b1[c * TT + frc];
        #pragma unroll
        for (int j = 0; j < 38; j++) breg[j] = bf_[2 + j];

        const bool wr = (k == WARMF);
        const int base = frc * HOP;
        float excv = src[base] * esc;

        for (int j = 0; j < HOP; j++) {
            // ---- stage-1 (mlsadf1), replicated within group ----
            float x  = excv * eb0;
            float m0 = fmaf(ALPHA, na0, AAC * x1p);
            float m1 = fmaf(ALPHA, na1, AAC * npt0);
            float m2 = fmaf(ALPHA, na2, AAC * npt1);
            float m3 = fmaf(ALPHA, na3, AAC * npt2);
            na0 = m0; na1 = m1; na2 = m2; na3 = m3;
            float p0 = m0 * b1, p1 = m1 * b1, p2 = m2 * b1, p3 = m3 * b1;
            float sA1 = fmaf(P3C, p2, P1C * p0);
            float sB1 = fmaf(P4C, p3, P2C * p1);
            float x1 = x + (sA1 - sB1);
            float y1 = x1 + (sA1 + sB1);
            x1p = x1; npt0 = p0; npt1 = p1; npt2 = p2;

            // prefetch next excitation sample (off critical path)
            if (j + 1 < HOP) excv = src[base + j + 1] * esc;

            // ---- stage-2 tap (mlsafir order recurrence), tap = sub ----
            float d1n = fmaf(ALPHA, d1o, AAC * xin);
            float pm1 = n[0];
            float nw  = fmaf(-ALPHA, d1n, fmaf(ALPHA, n[0], d1o));
            float y   = nw * breg[0];
            n[0] = nw;
            #pragma unroll
            for (int m = 1; m < 38; m++) {
                float cc = fmaf(ALPHA, n[m], pm1);   // off-chain
                pm1 = n[m];
                nw  = fmaf(-ALPHA, nw, cc);          // 4-cyc chain
                y   = fmaf(nw, breg[m], y);          // off-chain accum
                n[m] = nw;
            }
            d1o = d1n;

            // ---- group-local exchange + Pade reduce ----
            float t0 = __shfl_sync(0xffffffffu, y, gb + 0);
            float t1 = __shfl_sync(0xffffffffu, y, gb + 1);
            float t2 = __shfl_sync(0xffffffffu, y, gb + 2);
            float t3 = __shfl_sync(0xffffffffu, y, gb + 3);
            float sA = fmaf(P3C, t2, P1C * t0);
            float sB = fmaf(P4C, t3, P2C * t1);
            float x2 = y1 + (sA - sB);
            float y2 = x2 + (sA + sB);
            if (sub == 0 && wr) atomicAdd(&oout[base + j], y2);  // REDG

            // next-sample tap inputs: [x2, fy0, fy1, fy2]
            xin = (sub == 0) ? x2
                : (sub == 1) ? t0
                : (sub == 2) ? t1
                : t2;
        }
    }
}

// ==================================================================
extern "C" void kernel_launch(void* const* d_in, const int* in_sizes, int n_in,
                              void* d_out, int out_size)
{
    const float* mceps = (const float*)d_in[0];
    const float* apdcs = (const float*)d_in[1];
    const float* f0s   = (const float*)d_in[2];
    const float* noise = (const float*)d_in[3];
    const float* Wm  = (const float*)d_in[4];
    const float* bm  = (const float*)d_in[5];
    const float* Wa  = (const float*)d_in[6];
    const float* ba  = (const float*)d_in[7];
    const float* Wf  = (const float*)d_in[8];
    const float* bf  = (const float*)d_in[9];
    const float* Wpa = (const float*)d_in[10];
    const float* bpa = (const float*)d_in[11];
    const float* Wpp = (const float*)d_in[12];
    const float* bpp = (const float*)d_in[13];
    const float* Wrp = (const float*)d_in[14];
    const float* brp = (const float*)d_in[15];
    const float* Wra = (const float*)d_in[16];
    const float* bra = (const float*)d_in[17];
    const float* Wap = (const float*)d_in[18];

    k_front_pulse<<<BB * (TT / TB) + BB, 256>>>(mceps, apdcs, f0s,
                                                Wm, bm, Wa, ba, Wf, bf,
                                                Wpa, bpa, Wpp, bpp,
                                                Wrp, brp, Wra, bra, Wap,
                                                (float*)d_out);
    k_mlsa<<<(NCH * SEG) / 8, 32>>>(noise, (float*)d_out);
}